// round 12
// baseline (speedup 1.0000x reference)
#include <cuda_runtime.h>
#include <cuda_bf16.h>
#include <cstdint>

#define DHID   512
#define KC     512
#define BM     64
#define BK     64          // K elems per chunk = 128 bytes bf16
#define NCH    (DHID/BK)   // 8 chunks
#define NT     512         // 16 warps

#define A_FULL  (BM * DHID * 2)        // 64 KB: full-K A tile, written once
#define B_STAGE (KC * 128)             // 64 KB per stage
#define DYN_SMEM (A_FULL + 2*B_STAGE + 1024)   // 192 KB + slack

__device__ __nv_bfloat16 g_wbf[KC * DHID];   // centers bf16, [n][k] row-major
__device__ float         g_c2[KC];

// ---------------------------------------------------------------------------
__device__ __forceinline__ uint32_t smem_u32(const void* p) {
    uint32_t a;
    asm("{ .reg .u64 t; cvta.to.shared.u64 t, %1; cvt.u32.u64 %0, t; }" : "=r"(a) : "l"(p));
    return a;
}
__device__ __forceinline__ uint32_t pack_bf16(float lo, float hi) {
    uint32_t r;
    asm("cvt.rn.bf16x2.f32 %0, %1, %2;" : "=r"(r) : "f"(hi), "f"(lo));
    return r;
}
#define SWZ128(o) ((o) ^ (((o) >> 3) & 0x70))

__device__ __forceinline__ void cp_async16(uint32_t dst, const void* src) {
    asm volatile("cp.async.cg.shared.global [%0], [%1], 16;\n" :: "r"(dst), "l"(src) : "memory");
}
#define CP_COMMIT() asm volatile("cp.async.commit_group;\n" ::: "memory")
#define CP_WAIT0()  asm volatile("cp.async.wait_group 0;\n" ::: "memory")

#define LDSM4(r, a) \
    asm volatile("ldmatrix.sync.aligned.m8n8.x4.shared.b16 {%0,%1,%2,%3}, [%4];" \
                 : "=r"((r)[0]), "=r"((r)[1]), "=r"((r)[2]), "=r"((r)[3]) : "r"(a))

#define MMA16816(d, a, b0, b1) \
    asm volatile("mma.sync.aligned.m16n8k16.row.col.f32.bf16.bf16.f32 " \
                 "{%0,%1,%2,%3}, {%4,%5,%6,%7}, {%8,%9}, {%0,%1,%2,%3};" \
                 : "+f"((d)[0]), "+f"((d)[1]), "+f"((d)[2]), "+f"((d)[3]) \
                 : "r"((a)[0]), "r"((a)[1]), "r"((a)[2]), "r"((a)[3]), \
                   "r"(b0), "r"(b1))

// ---------------------------------------------------------------------------
// Prep W: centers fp32 -> bf16 + ||c||^2. One block per cluster row.
// ---------------------------------------------------------------------------
__global__ void prep_w_kernel(const float* __restrict__ centers) {
    const int c = blockIdx.x, t = threadIdx.x;       // 256 threads
    const float2* row = reinterpret_cast<const float2*>(centers + (size_t)c * DHID);
    float2 v = row[t];
    reinterpret_cast<uint32_t*>(g_wbf + (size_t)c * DHID)[t] = pack_bf16(v.x, v.y);
    float s = v.x * v.x + v.y * v.y;
    #pragma unroll
    for (int o = 16; o > 0; o >>= 1) s += __shfl_xor_sync(0xffffffffu, s, o);
    __shared__ float ws[8];
    if ((t & 31) == 0) ws[t >> 5] = s;
    __syncthreads();
    if (t == 0) {
        float tot = 0.f;
        #pragma unroll
        for (int i = 0; i < 8; i++) tot += ws[i];
        g_c2[c] = tot;
    }
}

// ---------------------------------------------------------------------------
// Main fused kernel: 64 rows x 512 clusters per CTA, 16 warps (64x32 per warp).
// A converted fp32->bf16 ONCE into a 64 KB full-K smem tile; loop stages only B.
// ---------------------------------------------------------------------------
extern __shared__ char dynsmem[];

__global__ __launch_bounds__(NT, 1)
void qsoft_mma_kernel(const float* __restrict__ x, float* __restrict__ out) {
    __shared__ float xs_sm[BM];
    __shared__ float c2s[KC];
    __shared__ float rs_sm[BM][16];
    __shared__ float inv_sm[BM];

    const int tid  = threadIdx.x;
    const int wid  = tid >> 5;
    const int lane = tid & 31;
    const int rowBase = blockIdx.x * BM;

    const uint32_t sbase = (smem_u32(dynsmem) + 1023u) & ~1023u;
    const uint32_t Abase = sbase;                     // 8 blocks of 8 KB (one per K-chunk)
    const uint32_t Bbuf[2] = { sbase + A_FULL, sbase + A_FULL + B_STAGE };

    // ldmatrix lane addressing (within-tile offsets)
    const int a_r  = ((lane >> 3) & 1) * 8 + (lane & 7);   // A row in m16
    const int a_kb = ((lane >> 4) & 1) * 16;               // A k-byte
    const int b_r  = ((lane >> 4) & 1) * 8 + (lane & 7);   // B row in n16
    const int b_kb = ((lane >> 3) & 1) * 16;               // B k-byte

    // ---------------- B loader (cp.async) ----------------
    auto ldb = [&](int c, int s) {
        #pragma unroll
        for (int k = 0; k < 8; k++) {
            int idx = tid + k * NT;
            int n = idx >> 3, i = idx & 7;
            const char* src = reinterpret_cast<const char*>(g_wbf)
                            + (size_t)n * (DHID * 2) + c * 128 + i * 16;
            uint32_t off = (uint32_t)n * 128u + (uint32_t)i * 16u;
            cp_async16(Bbuf[s] + SWZ128(off), src);
        }
    };

    // ---------------- kick off B chunk 0, then convert A (overlapped) --------
    ldb(0, 0); CP_COMMIT();

    {
        // thread t: row t>>3, K-chunk t&7 -> one swizzled 128B block-row
        const int arow = tid >> 3;
        const int ach  = tid & 7;
        const float4* src = reinterpret_cast<const float4*>(
            x + (size_t)(rowBase + arow) * DHID + ach * BK);
        const uint32_t adst = Abase + (uint32_t)ach * 8192u;
        float sq = 0.f;
        #pragma unroll
        for (int i = 0; i < 8; i++) {
            float4 u = src[2*i], v = src[2*i+1];
            sq += u.x*u.x + u.y*u.y + u.z*u.z + u.w*u.w
                + v.x*v.x + v.y*v.y + v.z*v.z + v.w*v.w;
            uint32_t p0 = pack_bf16(u.x, u.y);
            uint32_t p1 = pack_bf16(u.z, u.w);
            uint32_t p2 = pack_bf16(v.x, v.y);
            uint32_t p3 = pack_bf16(v.z, v.w);
            asm volatile("st.shared.v4.b32 [%0], {%1,%2,%3,%4};"
                         :: "r"(adst + SWZ128((uint32_t)arow * 128u + (uint32_t)i * 16u)),
                            "r"(p0), "r"(p1), "r"(p2), "r"(p3) : "memory");
        }
        // ||x||^2: 8 consecutive lanes own one row
        sq += __shfl_xor_sync(0xffffffffu, sq, 1);
        sq += __shfl_xor_sync(0xffffffffu, sq, 2);
        sq += __shfl_xor_sync(0xffffffffu, sq, 4);
        if ((tid & 7) == 0) xs_sm[arow] = sq;
    }

    float acc[4][4][4];
    #pragma unroll
    for (int mi = 0; mi < 4; mi++)
        #pragma unroll
        for (int ni = 0; ni < 4; ni++)
            #pragma unroll
            for (int e = 0; e < 4; e++) acc[mi][ni][e] = 0.f;

    // ---------------- compute one K-chunk (warp: 64 rows x 32 cols) ----------
    auto compute = [&](int c, int s) {
        const uint32_t Ab = Abase + (uint32_t)c * 8192u;
        const uint32_t Bb = Bbuf[s];
        #pragma unroll
        for (int ks = 0; ks < 4; ks++) {
            uint32_t b[2][4], a[4][4];
            #pragma unroll
            for (int j = 0; j < 2; j++) {
                uint32_t off = (uint32_t)(wid * 32 + j * 16 + b_r) * 128u
                             + (uint32_t)(ks * 32 + b_kb);
                LDSM4(b[j], Bb + SWZ128(off));
            }
            #pragma unroll
            for (int mi = 0; mi < 4; mi++) {
                uint32_t off = (uint32_t)(mi * 16 + a_r) * 128u
                             + (uint32_t)(ks * 32 + a_kb);
                LDSM4(a[mi], Ab + SWZ128(off));
            }
            #pragma unroll
            for (int mi = 0; mi < 4; mi++) {
                MMA16816(acc[mi][0], a[mi], b[0][0], b[0][1]);
                MMA16816(acc[mi][1], a[mi], b[0][2], b[0][3]);
                MMA16816(acc[mi][2], a[mi], b[1][0], b[1][1]);
                MMA16816(acc[mi][3], a[mi], b[1][2], b[1][3]);
            }
        }
    };

    // ---------------- pipeline (2-stage B double buffer, A resident) ---------
    CP_WAIT0(); __syncthreads();

    for (int c = 0; c < NCH; c++) {
        const int s = c & 1;
        if (c + 1 < NCH) { ldb(c + 1, s ^ 1); CP_COMMIT(); }
        compute(c, s);
        if (c + 1 < NCH) CP_WAIT0();
        __syncthreads();
    }

    // ---------------- epilogue ----------------
    for (int i = tid; i < KC; i += NT) c2s[i] = g_c2[i];
    __syncthreads();

    const int qrow = lane >> 2;            // 0..7
    const int wcol = wid * 32 + (lane & 3) * 2;

    float rsum[8];
    #pragma unroll
    for (int i = 0; i < 8; i++) rsum[i] = 0.f;

    #pragma unroll
    for (int mi = 0; mi < 4; mi++) {
        const float x20 = xs_sm[mi * 16 + qrow];
        const float x21 = xs_sm[mi * 16 + qrow + 8];
        #pragma unroll
        for (int ni = 0; ni < 4; ni++) {
            const float cc0 = c2s[wcol + ni * 8];
            const float cc1 = c2s[wcol + ni * 8 + 1];
            float q0 = __fdividef(1.f, 1.f + fmaxf(fmaf(-2.f, acc[mi][ni][0], x20 + cc0), 0.f));
            float q1 = __fdividef(1.f, 1.f + fmaxf(fmaf(-2.f, acc[mi][ni][1], x20 + cc1), 0.f));
            float q2 = __fdividef(1.f, 1.f + fmaxf(fmaf(-2.f, acc[mi][ni][2], x21 + cc0), 0.f));
            float q3 = __fdividef(1.f, 1.f + fmaxf(fmaf(-2.f, acc[mi][ni][3], x21 + cc1), 0.f));
            acc[mi][ni][0] = q0; acc[mi][ni][1] = q1;
            acc[mi][ni][2] = q2; acc[mi][ni][3] = q3;
            rsum[2*mi]   += q0 + q1;
            rsum[2*mi+1] += q2 + q3;
        }
    }
    #pragma unroll
    for (int i = 0; i < 8; i++) {
        float v = rsum[i];
        v += __shfl_xor_sync(0xffffffffu, v, 1);
        v += __shfl_xor_sync(0xffffffffu, v, 2);
        rsum[i] = v;
    }
    if ((lane & 3) == 0) {
        #pragma unroll
        for (int mi = 0; mi < 4; mi++) {
            rs_sm[mi * 16 + qrow][wid]     = rsum[2*mi];
            rs_sm[mi * 16 + qrow + 8][wid] = rsum[2*mi+1];
        }
    }
    __syncthreads();
    if (tid < BM) {
        float t = 0.f;
        #pragma unroll
        for (int w = 0; w < 16; w++) t += rs_sm[tid][w];
        inv_sm[tid] = __fdividef(1.f, t);
    }
    __syncthreads();

    #pragma unroll
    for (int mi = 0; mi < 4; mi++) {
        const int r0 = mi * 16 + qrow, r1 = r0 + 8;
        const float inv0 = inv_sm[r0], inv1 = inv_sm[r1];
        float* o0 = out + (size_t)(rowBase + r0) * KC + wcol;
        float* o1 = out + (size_t)(rowBase + r1) * KC + wcol;
        #pragma unroll
        for (int ni = 0; ni < 4; ni++) {
            *reinterpret_cast<float2*>(o0 + ni * 8) =
                make_float2(acc[mi][ni][0] * inv0, acc[mi][ni][1] * inv0);
            *reinterpret_cast<float2*>(o1 + ni * 8) =
                make_float2(acc[mi][ni][2] * inv1, acc[mi][ni][3] * inv1);
        }
    }
}

// ---------------------------------------------------------------------------
extern "C" void kernel_launch(void* const* d_in, const int* in_sizes, int n_in,
                              void* d_out, int out_size) {
    const float* x       = (const float*)d_in[0];
    const float* centers = (const float*)d_in[1];
    float*       out     = (float*)d_out;
    const int N = in_sizes[0] / DHID;   // 131072

    cudaFuncSetAttribute(qsoft_mma_kernel,
                         cudaFuncAttributeMaxDynamicSharedMemorySize, DYN_SMEM);

    prep_w_kernel<<<KC, 256>>>(centers);
    qsoft_mma_kernel<<<N / BM, NT, DYN_SMEM>>>(x, out);
}

// round 13
// speedup vs baseline: 1.5989x; 1.5989x over previous
#include <cuda_runtime.h>
#include <cuda_fp16.h>
#include <cstdint>

#define DHID   512
#define KC     512
#define BM     128         // rows per CTA
#define BK     64          // K elems per chunk = 128 bytes fp16
#define NCH    (DHID/BK)   // 8 chunks
#define NT     512         // 16 warps, each owns 128x32 output tile

#define A_STAGE (BM * 128)             // 16 KB
#define B_STAGE (KC * 128)             // 64 KB
#define DYN_SMEM (2*(A_STAGE + B_STAGE) + 1024)   // 160 KB + slack

__device__ __half g_wh[KC * DHID];   // centers fp16, [n][k] row-major
__device__ float  g_c2[KC];

// ---------------------------------------------------------------------------
__device__ __forceinline__ uint32_t smem_u32(const void* p) {
    uint32_t a;
    asm("{ .reg .u64 t; cvta.to.shared.u64 t, %1; cvt.u32.u64 %0, t; }" : "=r"(a) : "l"(p));
    return a;
}
__device__ __forceinline__ uint32_t pack_f16(float lo, float hi) {
    uint32_t r;
    asm("cvt.rn.f16x2.f32 %0, %1, %2;" : "=r"(r) : "f"(hi), "f"(lo));
    return r;
}
__device__ __forceinline__ float2 unpack_f16(uint32_t u) {
    __half2 h = *reinterpret_cast<__half2*>(&u);
    return __half22float2(h);
}
#define SWZ128(o) ((o) ^ (((o) >> 3) & 0x70))

__device__ __forceinline__ void cp_async16(uint32_t dst, const void* src) {
    asm volatile("cp.async.cg.shared.global [%0], [%1], 16;\n" :: "r"(dst), "l"(src) : "memory");
}
#define CP_COMMIT() asm volatile("cp.async.commit_group;\n" ::: "memory")
#define CP_WAIT0()  asm volatile("cp.async.wait_group 0;\n" ::: "memory")

#define LDSM4(r, a) \
    asm volatile("ldmatrix.sync.aligned.m8n8.x4.shared.b16 {%0,%1,%2,%3}, [%4];" \
                 : "=r"((r)[0]), "=r"((r)[1]), "=r"((r)[2]), "=r"((r)[3]) : "r"(a))

// fp16 inputs, fp16 accumulators: D/C are 2 b32 regs (4 halves)
#define MMAF16(d, a, b0, b1) \
    asm volatile("mma.sync.aligned.m16n8k16.row.col.f16.f16.f16.f16 " \
                 "{%0,%1}, {%2,%3,%4,%5}, {%6,%7}, {%0,%1};" \
                 : "+r"((d)[0]), "+r"((d)[1]) \
                 : "r"((a)[0]), "r"((a)[1]), "r"((a)[2]), "r"((a)[3]), \
                   "r"(b0), "r"(b1))

// ---------------------------------------------------------------------------
// Prep W: centers fp32 -> fp16 + ||c||^2. One block per cluster row.
// ---------------------------------------------------------------------------
__global__ void prep_w_kernel(const float* __restrict__ centers) {
    const int c = blockIdx.x, t = threadIdx.x;       // 256 threads
    const float2* row = reinterpret_cast<const float2*>(centers + (size_t)c * DHID);
    float2 v = row[t];
    reinterpret_cast<uint32_t*>(g_wh + (size_t)c * DHID)[t] = pack_f16(v.x, v.y);
    float s = v.x * v.x + v.y * v.y;
    #pragma unroll
    for (int o = 16; o > 0; o >>= 1) s += __shfl_xor_sync(0xffffffffu, s, o);
    __shared__ float ws[8];
    if ((t & 31) == 0) ws[t >> 5] = s;
    __syncthreads();
    if (t == 0) {
        float tot = 0.f;
        #pragma unroll
        for (int i = 0; i < 8; i++) tot += ws[i];
        g_c2[c] = tot;
    }
}

// ---------------------------------------------------------------------------
// Main fused kernel: 128 rows x 512 clusters per CTA, 16 warps (128x32 each).
// ---------------------------------------------------------------------------
extern __shared__ char dynsmem[];

__global__ __launch_bounds__(NT, 1)
void qsoft_mma_kernel(const float* __restrict__ x, float* __restrict__ out) {
    __shared__ float xs_sm[BM];
    __shared__ float c2s[KC];
    __shared__ float rs_sm[BM][16];
    __shared__ float inv_sm[BM];

    const int tid  = threadIdx.x;
    const int wid  = tid >> 5;
    const int lane = tid & 31;
    const int rowBase = blockIdx.x * BM;

    const uint32_t sbase = (smem_u32(dynsmem) + 1023u) & ~1023u;
    const uint32_t Abuf[2] = { sbase,              sbase + A_STAGE };
    const uint32_t Bbuf[2] = { sbase + 2*A_STAGE,  sbase + 2*A_STAGE + B_STAGE };

    // ---- A mapping: row = tid/4 (0..127), 16 floats at col (tid%4)*16 ----
    const int arow = tid >> 2;
    const int asub = tid & 3;

    // ldmatrix lane addressing (within-tile offsets)
    const int a_r  = ((lane >> 3) & 1) * 8 + (lane & 7);   // A row in m16
    const int a_kb = ((lane >> 4) & 1) * 16;               // A k-byte
    const int b_r  = ((lane >> 4) & 1) * 8 + (lane & 7);   // B row in n16
    const int b_kb = ((lane >> 3) & 1) * 16;               // B k-byte

    uint32_t acc[8][4][2];
    #pragma unroll
    for (int mi = 0; mi < 8; mi++)
        #pragma unroll
        for (int ni = 0; ni < 4; ni++) { acc[mi][ni][0] = 0u; acc[mi][ni][1] = 0u; }

    float sq = 0.f;
    float4 f[4];

    // ---------------- loaders ----------------
    auto lda = [&](int c) {
        const float4* src = reinterpret_cast<const float4*>(
            x + (size_t)(rowBase + arow) * DHID + c * BK + asub * 16);
        #pragma unroll
        for (int i = 0; i < 4; i++) f[i] = src[i];
    };
    auto sta = [&](int s) {
        #pragma unroll
        for (int i = 0; i < 4; i++)
            sq += f[i].x*f[i].x + f[i].y*f[i].y + f[i].z*f[i].z + f[i].w*f[i].w;
        #pragma unroll
        for (int h = 0; h < 2; h++) {
            uint32_t p0 = pack_f16(f[2*h].x,   f[2*h].y);
            uint32_t p1 = pack_f16(f[2*h].z,   f[2*h].w);
            uint32_t p2 = pack_f16(f[2*h+1].x, f[2*h+1].y);
            uint32_t p3 = pack_f16(f[2*h+1].z, f[2*h+1].w);
            uint32_t off = (uint32_t)arow * 128u + (uint32_t)asub * 32u + h * 16u;
            asm volatile("st.shared.v4.b32 [%0], {%1,%2,%3,%4};"
                         :: "r"(Abuf[s] + SWZ128(off)),
                            "r"(p0), "r"(p1), "r"(p2), "r"(p3) : "memory");
        }
    };
    auto ldb = [&](int c, int s) {
        #pragma unroll
        for (int k = 0; k < 8; k++) {
            int idx = tid + k * NT;
            int n = idx >> 3, i = idx & 7;
            const char* src = reinterpret_cast<const char*>(g_wh)
                            + (size_t)n * (DHID * 2) + c * 128 + i * 16;
            uint32_t off = (uint32_t)n * 128u + (uint32_t)i * 16u;
            cp_async16(Bbuf[s] + SWZ128(off), src);
        }
    };

    // ---------------- compute one K-chunk (warp: 128 rows x 32 cols) --------
    auto compute = [&](int s) {
        const uint32_t Ab = Abuf[s], Bb = Bbuf[s];
        #pragma unroll
        for (int ks = 0; ks < 4; ks++) {
            uint32_t b[2][4];
            #pragma unroll
            for (int j = 0; j < 2; j++) {
                uint32_t off = (uint32_t)(wid * 32 + j * 16 + b_r) * 128u
                             + (uint32_t)(ks * 32 + b_kb);
                LDSM4(b[j], Bb + SWZ128(off));
            }
            #pragma unroll
            for (int half = 0; half < 2; half++) {
                uint32_t a[4][4];
                #pragma unroll
                for (int i = 0; i < 4; i++) {
                    int mi = half * 4 + i;
                    uint32_t off = (uint32_t)(mi * 16 + a_r) * 128u
                                 + (uint32_t)(ks * 32 + a_kb);
                    LDSM4(a[i], Ab + SWZ128(off));
                }
                #pragma unroll
                for (int i = 0; i < 4; i++) {
                    int mi = half * 4 + i;
                    MMAF16(acc[mi][0], a[i], b[0][0], b[0][1]);
                    MMAF16(acc[mi][1], a[i], b[0][2], b[0][3]);
                    MMAF16(acc[mi][2], a[i], b[1][0], b[1][1]);
                    MMAF16(acc[mi][3], a[i], b[1][2], b[1][3]);
                }
            }
        }
    };

    // ---------------- pipeline (2-stage double buffer) ----------------
    lda(0);
    ldb(0, 0); CP_COMMIT();
    sta(0);
    CP_WAIT0(); __syncthreads();

    for (int c = 0; c < NCH; c++) {
        const int s = c & 1;
        if (c + 1 < NCH) { lda(c + 1); ldb(c + 1, s ^ 1); CP_COMMIT(); }
        compute(s);
        if (c + 1 < NCH) { sta(s ^ 1); CP_WAIT0(); }
        __syncthreads();
    }

    // ---------------- epilogue ----------------
    // ||x||^2: 4 lanes own one row -> xor 1,2
    sq += __shfl_xor_sync(0xffffffffu, sq, 1);
    sq += __shfl_xor_sync(0xffffffffu, sq, 2);
    if ((tid & 3) == 0) xs_sm[arow] = sq;
    for (int i = tid; i < KC; i += NT) c2s[i] = g_c2[i];
    __syncthreads();

    const int qrow = lane >> 2;            // 0..7
    const int wcol = wid * 32 + (lane & 3) * 2;

    // pass 1: row sums of q
    #pragma unroll
    for (int mi = 0; mi < 8; mi++) {
        const int r0 = mi * 16 + qrow, r1 = r0 + 8;
        const float x20 = xs_sm[r0], x21 = xs_sm[r1];
        float s0 = 0.f, s1 = 0.f;
        #pragma unroll
        for (int ni = 0; ni < 4; ni++) {
            const float cc0 = c2s[wcol + ni * 8];
            const float cc1 = c2s[wcol + ni * 8 + 1];
            float2 v0 = unpack_f16(acc[mi][ni][0]);   // (r0,c), (r0,c+1)
            float2 v1 = unpack_f16(acc[mi][ni][1]);   // (r1,c), (r1,c+1)
            s0 += __fdividef(1.f, 1.f + fmaxf(fmaf(-2.f, v0.x, x20 + cc0), 0.f))
                + __fdividef(1.f, 1.f + fmaxf(fmaf(-2.f, v0.y, x20 + cc1), 0.f));
            s1 += __fdividef(1.f, 1.f + fmaxf(fmaf(-2.f, v1.x, x21 + cc0), 0.f))
                + __fdividef(1.f, 1.f + fmaxf(fmaf(-2.f, v1.y, x21 + cc1), 0.f));
        }
        s0 += __shfl_xor_sync(0xffffffffu, s0, 1);
        s0 += __shfl_xor_sync(0xffffffffu, s0, 2);
        s1 += __shfl_xor_sync(0xffffffffu, s1, 1);
        s1 += __shfl_xor_sync(0xffffffffu, s1, 2);
        if ((lane & 3) == 0) { rs_sm[r0][wid] = s0; rs_sm[r1][wid] = s1; }
    }
    __syncthreads();
    if (tid < BM) {
        float t = 0.f;
        #pragma unroll
        for (int w = 0; w < 16; w++) t += rs_sm[tid][w];
        inv_sm[tid] = __fdividef(1.f, t);
    }
    __syncthreads();

    // pass 2: recompute q, scale, store
    #pragma unroll
    for (int mi = 0; mi < 8; mi++) {
        const int r0 = mi * 16 + qrow, r1 = r0 + 8;
        const float x20 = xs_sm[r0], x21 = xs_sm[r1];
        const float inv0 = inv_sm[r0], inv1 = inv_sm[r1];
        float* o0 = out + (size_t)(rowBase + r0) * KC + wcol;
        float* o1 = out + (size_t)(rowBase + r1) * KC + wcol;
        #pragma unroll
        for (int ni = 0; ni < 4; ni++) {
            const float cc0 = c2s[wcol + ni * 8];
            const float cc1 = c2s[wcol + ni * 8 + 1];
            float2 v0 = unpack_f16(acc[mi][ni][0]);
            float2 v1 = unpack_f16(acc[mi][ni][1]);
            float q00 = __fdividef(inv0, 1.f + fmaxf(fmaf(-2.f, v0.x, x20 + cc0), 0.f));
            float q01 = __fdividef(inv0, 1.f + fmaxf(fmaf(-2.f, v0.y, x20 + cc1), 0.f));
            float q10 = __fdividef(inv1, 1.f + fmaxf(fmaf(-2.f, v1.x, x21 + cc0), 0.f));
            float q11 = __fdividef(inv1, 1.f + fmaxf(fmaf(-2.f, v1.y, x21 + cc1), 0.f));
            *reinterpret_cast<float2*>(o0 + ni * 8) = make_float2(q00, q01);
            *reinterpret_cast<float2*>(o1 + ni * 8) = make_float2(q10, q11);
        }
    }
}

// ---------------------------------------------------------------------------
extern "C" void kernel_launch(void* const* d_in, const int* in_sizes, int n_in,
                              void* d_out, int out_size) {
    const float* x       = (const float*)d_in[0];
    const float* centers = (const float*)d_in[1];
    float*       out     = (float*)d_out;
    const int N = in_sizes[0] / DHID;   // 131072

    cudaFuncSetAttribute(qsoft_mma_kernel,
                         cudaFuncAttributeMaxDynamicSharedMemorySize, DYN_SMEM);

    prep_w_kernel<<<KC, 256>>>(centers);
    qsoft_mma_kernel<<<N / BM, NT, DYN_SMEM>>>(x, out);
}